// round 3
// baseline (speedup 1.0000x reference)
#include <cuda_runtime.h>

// PWLU channelwise piecewise-linear unit.
// x: [B=32, C=256, H=56, W=56] f32 (contiguous), points: [C=256, P=7] f32.
// out = left[c][r] + (xn - r) * diff[c][r],
//   xn = (x + 2.7) / 0.9, r = (int)clip(xn, 0, 5)
//
// One block of 128 threads per (b,c) slab of 3136 floats = 784 float4.
// Each thread front-batches 6 LDG.128 (threads 0..15 a 7th, predicated)
// -> MLP 6-7 per thread before any dependent compute.
// Table is warp-private in smem: no __syncthreads anywhere.

#define PWLU_NREG 6
#define PWLU_NPTS 7
#define PWLU_HW   3136
#define PWLU_HW4  784
#define PWLU_C    256

__device__ __forceinline__ float pwlu1(float v, const float2* __restrict__ tab)
{
    const float inv_rl = 1.0f / 0.9f;
    const float bias   = 2.7f * (1.0f / 0.9f);   // = 3.0 (region offset)
    float xn = fmaf(v, inv_rl, bias);
    float xc = fminf(fmaxf(xn, 0.0f), 5.0f);
    int   r  = (int)xc;                 // trunc == floor (xc >= 0)
    float d  = xn - (float)r;
    float2 ld = tab[r];                 // (left, diff) in one LDS.64
    return fmaf(d, ld.y, ld.x);
}

__device__ __forceinline__ float4 pwlu4(float4 v, const float2* __restrict__ tab)
{
    float4 o;
    o.x = pwlu1(v.x, tab);
    o.y = pwlu1(v.y, tab);
    o.z = pwlu1(v.z, tab);
    o.w = pwlu1(v.w, tab);
    return o;
}

__global__ __launch_bounds__(128, 10) void pwlu_kernel(
    const float* __restrict__ x,
    const float* __restrict__ points,
    float* __restrict__ out)
{
    const int slab = blockIdx.x;                 // b * C + c
    const int c    = slab & (PWLU_C - 1);
    const int t    = threadIdx.x;
    const int warp = t >> 5;
    const int lane = t & 31;

    const float4* __restrict__ xv =
        reinterpret_cast<const float4*>(x) + (size_t)slab * PWLU_HW4;
    float4* __restrict__ ov =
        reinterpret_cast<float4*>(out) + (size_t)slab * PWLU_HW4;

    // ---- front-batched independent global loads (MLP 6-7 per thread) ----
    float4 v0 = xv[t];
    float4 v1 = xv[t + 128];
    float4 v2 = xv[t + 256];
    float4 v3 = xv[t + 384];
    float4 v4 = xv[t + 512];
    float4 v5 = xv[t + 640];
    const bool rem = (t < (PWLU_HW4 - 768));     // 16 leftover float4
    float4 v6;
    if (rem) v6 = xv[t + 768];

    // ---- warp-private table: no block barrier, only __syncwarp ----
    __shared__ float2 s_tab[4][PWLU_NREG];
    if (lane < PWLU_NREG) {
        float p0 = points[c * PWLU_NPTS + lane];
        float p1 = points[c * PWLU_NPTS + lane + 1];
        s_tab[warp][lane] = make_float2(p0, p1 - p0);
    }
    __syncwarp();
    const float2* __restrict__ tab = s_tab[warp];

    // ---- compute + store ----
    ov[t]       = pwlu4(v0, tab);
    ov[t + 128] = pwlu4(v1, tab);
    ov[t + 256] = pwlu4(v2, tab);
    ov[t + 384] = pwlu4(v3, tab);
    ov[t + 512] = pwlu4(v4, tab);
    ov[t + 640] = pwlu4(v5, tab);
    if (rem) {
        ov[t + 768] = pwlu4(v6, tab);
    }
}

extern "C" void kernel_launch(void* const* d_in, const int* in_sizes, int n_in,
                              void* d_out, int out_size)
{
    const float* x      = (const float*)d_in[0];
    const float* points = (const float*)d_in[1];
    float* out          = (float*)d_out;

    const int n_slabs = in_sizes[0] / PWLU_HW;   // B * C = 8192
    pwlu_kernel<<<n_slabs, 128>>>(x, points, out);
}

// round 5
// speedup vs baseline: 1.0174x; 1.0174x over previous
#include <cuda_runtime.h>

// PWLU channelwise piecewise-linear unit.
// x: [B=32, C=256, H=56, W=56] f32 (contiguous), points: [C=256, P=7] f32.
// out = left[c][r] + (xn - r) * diff[c][r],
//   xn = (x + 2.7) / 0.9, r = (int)clip(xn, 0, 5)
//
// One block of 256 threads per (b,c) slab of 3136 floats = 784 float4.
// 3 (+1 predicated) front-batched LDG.128 per thread.
// x loads carry an L2::evict_last cache policy (createpolicy + cache_hint,
// since the bare qualifier needs 256-bit ops on sm_103); out uses st.global.cs.

#define PWLU_NREG 6
#define PWLU_NPTS 7
#define PWLU_HW   3136
#define PWLU_HW4  784
#define PWLU_C    256

__device__ __forceinline__ unsigned long long mk_policy_keep()
{
    unsigned long long pol;
    asm("createpolicy.fractional.L2::evict_last.b64 %0, 1.0;" : "=l"(pol));
    return pol;
}

__device__ __forceinline__ float4 ldg_keep(const float4* p, unsigned long long pol)
{
    float4 v;
    asm("ld.global.nc.L2::cache_hint.v4.f32 {%0,%1,%2,%3}, [%4], %5;"
        : "=f"(v.x), "=f"(v.y), "=f"(v.z), "=f"(v.w)
        : "l"(p), "l"(pol));
    return v;
}

__device__ __forceinline__ void stg_stream(float4* p, float4 v)
{
    asm volatile("st.global.cs.v4.f32 [%0], {%1,%2,%3,%4};"
                 :: "l"(p), "f"(v.x), "f"(v.y), "f"(v.z), "f"(v.w)
                 : "memory");
}

__device__ __forceinline__ float pwlu1(float v, const float2* __restrict__ tab)
{
    const float inv_rl = 1.0f / 0.9f;
    const float bias   = 2.7f * (1.0f / 0.9f);   // = 3.0 (region offset)
    float xn = fmaf(v, inv_rl, bias);
    float xc = fminf(fmaxf(xn, 0.0f), 5.0f);
    int   r  = (int)xc;                 // trunc == floor (xc >= 0)
    float d  = xn - (float)r;
    float2 ld = tab[r];                 // (left, diff) in one LDS.64
    return fmaf(d, ld.y, ld.x);
}

__device__ __forceinline__ float4 pwlu4(float4 v, const float2* __restrict__ tab)
{
    float4 o;
    o.x = pwlu1(v.x, tab);
    o.y = pwlu1(v.y, tab);
    o.z = pwlu1(v.z, tab);
    o.w = pwlu1(v.w, tab);
    return o;
}

__global__ __launch_bounds__(256) void pwlu_kernel(
    const float* __restrict__ x,
    const float* __restrict__ points,
    float* __restrict__ out)
{
    const int slab = blockIdx.x;                 // b * C + c
    const int c    = slab & (PWLU_C - 1);
    const int t    = threadIdx.x;
    const int warp = t >> 5;
    const int lane = t & 31;

    const float4* __restrict__ xv =
        reinterpret_cast<const float4*>(x) + (size_t)slab * PWLU_HW4;
    float4* __restrict__ ov =
        reinterpret_cast<float4*>(out) + (size_t)slab * PWLU_HW4;

    const unsigned long long pol = mk_policy_keep();

    // ---- front-batched independent global loads (MLP 3-4 per thread) ----
    float4 v0 = ldg_keep(xv + t,       pol);
    float4 v1 = ldg_keep(xv + t + 256, pol);
    float4 v2 = ldg_keep(xv + t + 512, pol);
    const bool rem = (t < (PWLU_HW4 - 768));     // 16 leftover float4
    float4 v3;
    if (rem) v3 = ldg_keep(xv + t + 768, pol);

    // ---- warp-private table: no block barrier, only __syncwarp ----
    __shared__ float2 s_tab[8][PWLU_NREG];
    if (lane < PWLU_NREG) {
        float p0 = points[c * PWLU_NPTS + lane];
        float p1 = points[c * PWLU_NPTS + lane + 1];
        s_tab[warp][lane] = make_float2(p0, p1 - p0);
    }
    __syncwarp();
    const float2* __restrict__ tab = s_tab[warp];

    // ---- compute + streaming stores ----
    stg_stream(ov + t,       pwlu4(v0, tab));
    stg_stream(ov + t + 256, pwlu4(v1, tab));
    stg_stream(ov + t + 512, pwlu4(v2, tab));
    if (rem) {
        stg_stream(ov + t + 768, pwlu4(v3, tab));
    }
}

extern "C" void kernel_launch(void* const* d_in, const int* in_sizes, int n_in,
                              void* d_out, int out_size)
{
    const float* x      = (const float*)d_in[0];
    const float* points = (const float*)d_in[1];
    float* out          = (float*)d_out;

    const int n_slabs = in_sizes[0] / PWLU_HW;   // B * C = 8192
    pwlu_kernel<<<n_slabs, 256>>>(x, points, out);
}